// round 1
// baseline (speedup 1.0000x reference)
#include <cuda_runtime.h>

#define BATCH 4
#define NV 4096
#define NM 8192
#define BIGF 1e10f
#define ENC_INF 0xFF7FFFFFu   // encoded FLT_MAX

// ------------------------ scratch (device globals, no allocs) ---------------
__device__ float4   g_vw[BATCH * NV];   // (vx,vy,vz, ||v||^2)
__device__ float4   g_pw[BATCH * NM];   // (-2px,-2py,-2pz, ||p||^2) or (0,0,0,BIG) if padded
__device__ unsigned g_d1[BATCH * NV];   // encoded min over p of d
__device__ unsigned g_d2[BATCH * NM];   // encoded min over v of d

// order-preserving float<->uint encoding so unsigned atomicMin == float min
__device__ __forceinline__ unsigned encf(float f) {
    unsigned u = __float_as_uint(f);
    return (u & 0x80000000u) ? ~u : (u | 0x80000000u);
}
__device__ __forceinline__ float decf(unsigned u) {
    return (u & 0x80000000u) ? __uint_as_float(u & 0x7FFFFFFFu)
                             : __uint_as_float(~u);
}

// ------------------------ 1) precompute + reset -----------------------------
__global__ void pre_kernel(const float* __restrict__ vert,
                           const float* __restrict__ pc) {
    int t = blockIdx.x * blockDim.x + threadIdx.x;
    if (t >= BATCH * NM) return;
    int b = t >> 13;          // / 8192
    int m = t & (NM - 1);

    float p0 = pc[(b * 3 + 0) * NM + m];
    float p1 = pc[(b * 3 + 1) * NM + m];
    float p2 = pc[(b * 3 + 2) * NM + m];
    bool valid = (p0 != 0.f) || (p1 != 0.f) || (p2 != 0.f);
    float cp = fmaf(p0, p0, fmaf(p1, p1, p2 * p2));
    float4 pw = valid ? make_float4(-2.f * p0, -2.f * p1, -2.f * p2, cp)
                      : make_float4(0.f, 0.f, 0.f, BIGF);
    g_pw[t] = pw;
    g_d2[t] = ENC_INF;

    if (m < NV) {
        int n = m;
        int i = n >> 6, k = n & 63;
        // vertices[b, c, i, 31, k]; shape (4,3,64,32,64)
        int base = ((b * 3) * 64 + i) * 2048 + 31 * 64 + k;
        float v0 = (vert[base]          - 0.5f) * 2.f;
        float v1 = (vert[base + 131072] - 0.5f) * 2.f;
        float v2 = (vert[base + 262144] - 0.5f) * 2.f;
        float cv = fmaf(v0, v0, fmaf(v1, v1, v2 * v2));
        g_vw[b * NV + n] = make_float4(v0, v1, v2, cv);
        g_d1[b * NV + n] = ENC_INF;
    }
}

// ------------------------ 2) fused pairwise min kernel ----------------------
#define BN 128
#define BM 128

__global__ __launch_bounds__(256, 4) void chamfer_kernel() {
    __shared__ float4 sv[BN];
    __shared__ float4 sp[BM];
    __shared__ float  sred[128 * 17];   // padded to kill bank conflicts

    int b  = blockIdx.z;
    int n0 = blockIdx.y * BN;
    int m0 = blockIdx.x * BM;
    int tid = threadIdx.x;

    if (tid < BN) sv[tid] = g_vw[b * NV + n0 + tid];
    else          sp[tid - BN] = g_pw[b * NM + m0 + (tid - BN)];
    __syncthreads();

    int ty = tid >> 4;     // 0..15 -> v rows ty + 16*i
    int tx = tid & 15;     // 0..15 -> p cols tx + 16*j

    float4 vr[8];
#pragma unroll
    for (int i = 0; i < 8; i++) vr[i] = sv[ty + 16 * i];

    float rmin[8], cmin[8];
#pragma unroll
    for (int i = 0; i < 8; i++) { rmin[i] = 3.4e38f; cmin[i] = 3.4e38f; }

#pragma unroll
    for (int j = 0; j < 8; j++) {
        float4 p = sp[tx + 16 * j];
#pragma unroll
        for (int i = 0; i < 8; i++) {
            // t1 = cp - 2 v.p ;  d = t1 + cv
            float t1 = fmaf(vr[i].x, p.x,
                       fmaf(vr[i].y, p.y,
                       fmaf(vr[i].z, p.z, p.w)));
            rmin[i] = fminf(rmin[i], t1);                 // cv added after the min
            cmin[j] = fminf(cmin[j], t1 + vr[i].w);       // full d for the p-side min
        }
    }

    // ---- dist1: reduce 16 partials per v row across tx ----
#pragma unroll
    for (int i = 0; i < 8; i++)
        sred[(ty + 16 * i) * 17 + tx] = rmin[i] + vr[i].w;
    __syncthreads();
    if (tid < BN) {
        float mn = sred[tid * 17];
#pragma unroll
        for (int k = 1; k < 16; k++) mn = fminf(mn, sred[tid * 17 + k]);
        atomicMin(&g_d1[b * NV + n0 + tid], encf(mn));
    }
    __syncthreads();

    // ---- dist2: reduce 16 partials per p col across ty ----
#pragma unroll
    for (int j = 0; j < 8; j++)
        sred[(tx + 16 * j) * 17 + ty] = cmin[j];
    __syncthreads();
    if (tid < BM) {
        float mn = sred[tid * 17];
#pragma unroll
        for (int k = 1; k < 16; k++) mn = fminf(mn, sred[tid * 17 + k]);
        atomicMin(&g_d2[b * NM + m0 + tid], encf(mn));
    }
}

// ------------------------ 3) final scalar reduction -------------------------
__global__ void final_kernel(float* __restrict__ out) {
    const int T = 256;
    __shared__ float sh[T];
    __shared__ float acc;
    int tid = threadIdx.x;
    if (tid == 0) acc = 0.f;

    for (int b = 0; b < BATCH; b++) {
        float s1 = 0.f;
        for (int n = tid; n < NV; n += T) s1 += decf(g_d1[b * NV + n]);
        sh[tid] = s1; __syncthreads();
        for (int s = T / 2; s > 0; s >>= 1) { if (tid < s) sh[tid] += sh[tid + s]; __syncthreads(); }
        float mean1 = sh[0] / (float)NV;
        __syncthreads();

        float s2 = 0.f, c2 = 0.f;
        for (int m = tid; m < NM; m += T) {
            float w = g_pw[b * NM + m].w;
            if (w < 1e9f) { s2 += decf(g_d2[b * NM + m]); c2 += 1.f; }
        }
        sh[tid] = s2; __syncthreads();
        for (int s = T / 2; s > 0; s >>= 1) { if (tid < s) sh[tid] += sh[tid + s]; __syncthreads(); }
        float sum2 = sh[0];
        __syncthreads();
        sh[tid] = c2; __syncthreads();
        for (int s = T / 2; s > 0; s >>= 1) { if (tid < s) sh[tid] += sh[tid + s]; __syncthreads(); }
        float cnt = sh[0];
        __syncthreads();

        if (tid == 0) acc += mean1 + sum2 / fmaxf(cnt, 1.f);
        __syncthreads();
    }
    if (tid == 0) out[0] = acc / (float)BATCH;
}

// ------------------------ launch --------------------------------------------
extern "C" void kernel_launch(void* const* d_in, const int* in_sizes, int n_in,
                              void* d_out, int out_size) {
    const float* vert = (const float*)d_in[0];
    const float* pc   = (const float*)d_in[1];
    // defensive: identify inputs by element count
    if (in_sizes[0] == BATCH * 3 * NM) {
        vert = (const float*)d_in[1];
        pc   = (const float*)d_in[0];
    }

    pre_kernel<<<(BATCH * NM + 255) / 256, 256>>>(vert, pc);
    dim3 grid(NM / BM, NV / BN, BATCH);
    chamfer_kernel<<<grid, 256>>>();
    final_kernel<<<1, 256>>>((float*)d_out);
}

// round 2
// speedup vs baseline: 1.0925x; 1.0925x over previous
#include <cuda_runtime.h>

#define BATCH 4
#define NV 4096
#define NM 8192
#define BIGF 1e10f
#define ENC_INF 0xFF7FFFFFu   // encoded FLT_MAX

typedef unsigned long long u64;

// ------------------------ scratch (device globals, no allocs) ---------------
__device__ float4   g_vw[BATCH * NV];   // (vx,vy,vz, ||v||^2)
__device__ float4   g_pw[BATCH * NM];   // (-2px,-2py,-2pz, ||p||^2) or (0,0,0,BIG)
__device__ unsigned g_d1[BATCH * NV];   // encoded min over p of d
__device__ unsigned g_d2[BATCH * NM];   // encoded min over v of d

// order-preserving float<->uint encoding so unsigned atomicMin == float min
__device__ __forceinline__ unsigned encf(float f) {
    unsigned u = __float_as_uint(f);
    return (u & 0x80000000u) ? ~u : (u | 0x80000000u);
}
__device__ __forceinline__ float decf(unsigned u) {
    return (u & 0x80000000u) ? __uint_as_float(u & 0x7FFFFFFFu)
                             : __uint_as_float(~u);
}

// ------------------------ packed f32x2 helpers ------------------------------
__device__ __forceinline__ u64 pack2(float lo, float hi) {
    u64 d;
    asm("mov.b64 %0, {%1, %2};" : "=l"(d) : "f"(lo), "f"(hi));
    return d;
}
__device__ __forceinline__ float2 unpack2(u64 v) {
    float2 r;
    asm("mov.b64 {%0, %1}, %2;" : "=f"(r.x), "=f"(r.y) : "l"(v));
    return r;
}
__device__ __forceinline__ u64 fma2(u64 a, u64 b, u64 c) {
    u64 d;
    asm("fma.rn.f32x2 %0, %1, %2, %3;" : "=l"(d) : "l"(a), "l"(b), "l"(c));
    return d;
}
__device__ __forceinline__ u64 add2(u64 a, u64 b) {
    u64 d;
    asm("add.rn.f32x2 %0, %1, %2;" : "=l"(d) : "l"(a), "l"(b));
    return d;
}

// ------------------------ 1) precompute + reset -----------------------------
__global__ void pre_kernel(const float* __restrict__ vert,
                           const float* __restrict__ pc) {
    int t = blockIdx.x * blockDim.x + threadIdx.x;
    if (t >= BATCH * NM) return;
    int b = t >> 13;          // / 8192
    int m = t & (NM - 1);

    float p0 = pc[(b * 3 + 0) * NM + m];
    float p1 = pc[(b * 3 + 1) * NM + m];
    float p2 = pc[(b * 3 + 2) * NM + m];
    bool valid = (p0 != 0.f) || (p1 != 0.f) || (p2 != 0.f);
    float cp = fmaf(p0, p0, fmaf(p1, p1, p2 * p2));
    float4 pw = valid ? make_float4(-2.f * p0, -2.f * p1, -2.f * p2, cp)
                      : make_float4(0.f, 0.f, 0.f, BIGF);
    g_pw[t] = pw;
    g_d2[t] = ENC_INF;

    if (m < NV) {
        int n = m;
        int i = n >> 6, k = n & 63;
        // vertices[b, c, i, 31, k]; shape (4,3,64,32,64)
        int base = ((b * 3) * 64 + i) * 2048 + 31 * 64 + k;
        float v0 = (vert[base]          - 0.5f) * 2.f;
        float v1 = (vert[base + 131072] - 0.5f) * 2.f;
        float v2 = (vert[base + 262144] - 0.5f) * 2.f;
        float cv = fmaf(v0, v0, fmaf(v1, v1, v2 * v2));
        g_vw[b * NV + n] = make_float4(v0, v1, v2, cv);
        g_d1[b * NV + n] = ENC_INF;
    }
}

// ------------------------ 2) fused pairwise min kernel ----------------------
// Tile: 128 v-rows x 128 p-cols per 256-thread block.
// Thread (ty,tx): ty=tid/16 owns v rows [8ty, 8ty+8) as 4 packed pairs;
//                 tx=tid%16 owns p cols tx+16j, j=0..7.
// Packed f32x2 math: two v rows per instruction.
__global__ __launch_bounds__(256, 3) void chamfer_kernel() {
    __shared__ __align__(16) float svx[128];
    __shared__ __align__(16) float svy[128];
    __shared__ __align__(16) float svz[128];
    __shared__ __align__(16) float svw[128];
    __shared__ float4 sp[128];
    __shared__ float  sred[128 * 17];   // padded to limit bank conflicts

    int b  = blockIdx.z;
    int n0 = blockIdx.y * 128;
    int m0 = blockIdx.x * 128;
    int tid = threadIdx.x;

    if (tid < 128) {
        float4 t = g_vw[b * NV + n0 + tid];
        svx[tid] = t.x; svy[tid] = t.y; svz[tid] = t.z; svw[tid] = t.w;
    } else {
        sp[tid - 128] = g_pw[b * NM + m0 + (tid - 128)];
    }
    __syncthreads();

    int ty = tid >> 4;     // 0..15
    int tx = tid & 15;     // 0..15

    // packed v components: pair q covers rows (8ty+2q, 8ty+2q+1)
    u64 vx2[4], vy2[4], vz2[4], cv2[4];
#pragma unroll
    for (int q = 0; q < 4; q++) {
        int r = 8 * ty + 2 * q;
        vx2[q] = *(const u64*)&svx[r];
        vy2[q] = *(const u64*)&svy[r];
        vz2[q] = *(const u64*)&svz[r];
        cv2[q] = *(const u64*)&svw[r];
    }

    float rmin[8], cmin[8];
#pragma unroll
    for (int k = 0; k < 8; k++) { rmin[k] = 3.4e38f; cmin[k] = 3.4e38f; }

#pragma unroll
    for (int j = 0; j < 8; j++) {
        float4 p = sp[tx + 16 * j];
        u64 pxx = pack2(p.x, p.x);
        u64 pyy = pack2(p.y, p.y);
        u64 pzz = pack2(p.z, p.z);
        u64 cpp = pack2(p.w, p.w);
#pragma unroll
        for (int q = 0; q < 4; q++) {
            // t = cp - 2 v.p   (for both rows of the pair)
            u64 t = fma2(vz2[q], pzz, cpp);
            t = fma2(vy2[q], pyy, t);
            t = fma2(vx2[q], pxx, t);
            float2 a = unpack2(t);
            rmin[2 * q]     = fminf(rmin[2 * q],     a.x);
            rmin[2 * q + 1] = fminf(rmin[2 * q + 1], a.y);
            // full d = t + cv for the p-side min
            u64 d = add2(t, cv2[q]);
            float2 e = unpack2(d);
            cmin[j] = fminf(cmin[j], fminf(e.x, e.y));
        }
    }

    // ---- dist1: rows 8ty+k, partials across tx ----
#pragma unroll
    for (int k = 0; k < 8; k++)
        sred[(8 * ty + k) * 17 + tx] = rmin[k];
    __syncthreads();
    if (tid < 128) {
        float mn = sred[tid * 17];
#pragma unroll
        for (int k = 1; k < 16; k++) mn = fminf(mn, sred[tid * 17 + k]);
        mn += svw[tid];   // add ||v||^2 once, after the min
        atomicMin(&g_d1[b * NV + n0 + tid], encf(mn));
    }
    __syncthreads();

    // ---- dist2: cols tx+16j, partials across ty ----
#pragma unroll
    for (int j = 0; j < 8; j++)
        sred[(tx + 16 * j) * 17 + ty] = cmin[j];
    __syncthreads();
    if (tid < 128) {
        float mn = sred[tid * 17];
#pragma unroll
        for (int k = 1; k < 16; k++) mn = fminf(mn, sred[tid * 17 + k]);
        atomicMin(&g_d2[b * NM + m0 + tid], encf(mn));
    }
}

// ------------------------ 3) final scalar reduction -------------------------
__global__ void final_kernel(float* __restrict__ out) {
    const int T = 256;
    __shared__ float sh[T];
    __shared__ float acc;
    int tid = threadIdx.x;
    if (tid == 0) acc = 0.f;

    for (int b = 0; b < BATCH; b++) {
        float s1 = 0.f;
        for (int n = tid; n < NV; n += T) s1 += decf(g_d1[b * NV + n]);
        sh[tid] = s1; __syncthreads();
        for (int s = T / 2; s > 0; s >>= 1) { if (tid < s) sh[tid] += sh[tid + s]; __syncthreads(); }
        float mean1 = sh[0] / (float)NV;
        __syncthreads();

        float s2 = 0.f, c2 = 0.f;
        for (int m = tid; m < NM; m += T) {
            float w = g_pw[b * NM + m].w;
            if (w < 1e9f) { s2 += decf(g_d2[b * NM + m]); c2 += 1.f; }
        }
        sh[tid] = s2; __syncthreads();
        for (int s = T / 2; s > 0; s >>= 1) { if (tid < s) sh[tid] += sh[tid + s]; __syncthreads(); }
        float sum2 = sh[0];
        __syncthreads();
        sh[tid] = c2; __syncthreads();
        for (int s = T / 2; s > 0; s >>= 1) { if (tid < s) sh[tid] += sh[tid + s]; __syncthreads(); }
        float cnt = sh[0];
        __syncthreads();

        if (tid == 0) acc += mean1 + sum2 / fmaxf(cnt, 1.f);
        __syncthreads();
    }
    if (tid == 0) out[0] = acc / (float)BATCH;
}

// ------------------------ launch --------------------------------------------
extern "C" void kernel_launch(void* const* d_in, const int* in_sizes, int n_in,
                              void* d_out, int out_size) {
    const float* vert = (const float*)d_in[0];
    const float* pc   = (const float*)d_in[1];
    if (in_sizes[0] == BATCH * 3 * NM) {   // defensive input identification
        vert = (const float*)d_in[1];
        pc   = (const float*)d_in[0];
    }

    pre_kernel<<<(BATCH * NM + 255) / 256, 256>>>(vert, pc);
    dim3 grid(NM / 128, NV / 128, BATCH);
    chamfer_kernel<<<grid, 256>>>();
    final_kernel<<<1, 256>>>((float*)d_out);
}

// round 3
// speedup vs baseline: 1.0965x; 1.0036x over previous
#include <cuda_runtime.h>

#define BATCH 4
#define NV 4096
#define NM 8192
#define BIGF 1e10f
#define ENC_INF 0xFF7FFFFFu   // encoded FLT_MAX

#define NSTRIP 2              // m-strips per batch
#define STRIPM (NM / NSTRIP)  // 4096
#define NTILE  (STRIPM / 128) // 32 tiles of 128 p-cols

typedef unsigned long long u64;

// ------------------------ scratch (device globals, no allocs) ---------------
__device__ float4   g_vw[BATCH * NV];   // (vx,vy,vz, ||v||^2)
__device__ float4   g_pw[BATCH * NM];   // (-2px,-2py,-2pz, ||p||^2) or (0,0,0,BIG)
__device__ unsigned g_d1[BATCH * NV];   // encoded min over p of d
__device__ unsigned g_d2[BATCH * NM];   // encoded min over v of d

// order-preserving float<->uint encoding so unsigned atomicMin == float min
__device__ __forceinline__ unsigned encf(float f) {
    unsigned u = __float_as_uint(f);
    return (u & 0x80000000u) ? ~u : (u | 0x80000000u);
}
__device__ __forceinline__ float decf(unsigned u) {
    return (u & 0x80000000u) ? __uint_as_float(u & 0x7FFFFFFFu)
                             : __uint_as_float(~u);
}

// ------------------------ packed f32x2 helpers ------------------------------
__device__ __forceinline__ u64 pack2(float lo, float hi) {
    u64 d;
    asm("mov.b64 %0, {%1, %2};" : "=l"(d) : "f"(lo), "f"(hi));
    return d;
}
__device__ __forceinline__ float2 unpack2(u64 v) {
    float2 r;
    asm("mov.b64 {%0, %1}, %2;" : "=f"(r.x), "=f"(r.y) : "l"(v));
    return r;
}
__device__ __forceinline__ u64 fma2(u64 a, u64 b, u64 c) {
    u64 d;
    asm("fma.rn.f32x2 %0, %1, %2, %3;" : "=l"(d) : "l"(a), "l"(b), "l"(c));
    return d;
}
__device__ __forceinline__ u64 add2(u64 a, u64 b) {
    u64 d;
    asm("add.rn.f32x2 %0, %1, %2;" : "=l"(d) : "l"(a), "l"(b));
    return d;
}

// ------------------------ 1) precompute + reset -----------------------------
__global__ void pre_kernel(const float* __restrict__ vert,
                           const float* __restrict__ pc) {
    int t = blockIdx.x * blockDim.x + threadIdx.x;
    if (t >= BATCH * NM) return;
    int b = t >> 13;          // / 8192
    int m = t & (NM - 1);

    float p0 = pc[(b * 3 + 0) * NM + m];
    float p1 = pc[(b * 3 + 1) * NM + m];
    float p2 = pc[(b * 3 + 2) * NM + m];
    bool valid = (p0 != 0.f) || (p1 != 0.f) || (p2 != 0.f);
    float cp = fmaf(p0, p0, fmaf(p1, p1, p2 * p2));
    float4 pw = valid ? make_float4(-2.f * p0, -2.f * p1, -2.f * p2, cp)
                      : make_float4(0.f, 0.f, 0.f, BIGF);
    g_pw[t] = pw;
    g_d2[t] = ENC_INF;

    if (m < NV) {
        int n = m;
        int i = n >> 6, k = n & 63;
        // vertices[b, c, i, 31, k]; shape (4,3,64,32,64)
        int base = ((b * 3) * 64 + i) * 2048 + 31 * 64 + k;
        float v0 = (vert[base]          - 0.5f) * 2.f;
        float v1 = (vert[base + 131072] - 0.5f) * 2.f;
        float v2 = (vert[base + 262144] - 0.5f) * 2.f;
        float cv = fmaf(v0, v0, fmaf(v1, v1, v2 * v2));
        g_vw[b * NV + n] = make_float4(v0, v1, v2, cv);
        g_d1[b * NV + n] = ENC_INF;
    }
}

// ------------------------ 2) fused pairwise min kernel ----------------------
// Block: 128 v-rows x 4096 p-cols (32 tiles of 128), 256 threads.
// Thread (ty,tx): ty=tid/16 owns v rows [8ty,8ty+8) as 4 packed pairs (regs);
//                 tx=tid%16 owns p cols tx+16j of the current tile.
// rmin (dist1 partial) lives in registers across all tiles; dist2 reduced and
// atomically committed per tile, overlapped with the next tile's smem fill.
__global__ __launch_bounds__(256, 2) void chamfer_kernel() {
    __shared__ float4 sp[2][128];      // double-buffered p tile
    __shared__ float  sred[128 * 17];  // padded: conflict-free for both phases

    int b    = blockIdx.z;
    int n0   = blockIdx.y * 128;
    int s    = blockIdx.x;                 // m-strip
    int pb   = b * NM + s * STRIPM;        // strip base in g_pw / g_d2
    int tid  = threadIdx.x;
    int ty   = tid >> 4;
    int tx   = tid & 15;

    // ---- load my 8 v-rows as packed pairs (registers, no smem) ----
    u64 vx2[4], vy2[4], vz2[4], cv2[4];
#pragma unroll
    for (int q = 0; q < 4; q++) {
        int r = n0 + 8 * ty + 2 * q;
        float4 a = g_vw[b * NV + r];
        float4 c = g_vw[b * NV + r + 1];
        vx2[q] = pack2(a.x, c.x);
        vy2[q] = pack2(a.y, c.y);
        vz2[q] = pack2(a.z, c.z);
        cv2[q] = pack2(a.w, c.w);
    }

    float rmin[8];
#pragma unroll
    for (int k = 0; k < 8; k++) rmin[k] = 3.4e38f;

    // ---- prologue: fill tile 0 ----
    if (tid >= 128) sp[0][tid - 128] = g_pw[pb + (tid - 128)];
    __syncthreads();

    for (int t = 0; t < NTILE; t++) {
        // prefetch next tile into registers (threads 128..255)
        float4 pn;
        if (tid >= 128 && t + 1 < NTILE)
            pn = g_pw[pb + (t + 1) * 128 + (tid - 128)];

        const float4* cur = sp[t & 1];
        float cmin[8];
#pragma unroll
        for (int j = 0; j < 8; j++) cmin[j] = 3.4e38f;

#pragma unroll
        for (int j = 0; j < 8; j++) {
            float4 p = cur[tx + 16 * j];
            u64 pxx = pack2(p.x, p.x);
            u64 pyy = pack2(p.y, p.y);
            u64 pzz = pack2(p.z, p.z);
            u64 cpp = pack2(p.w, p.w);
#pragma unroll
            for (int q = 0; q < 4; q++) {
                // tq = cp - 2 v.p  (both rows of the pair)
                u64 tq = fma2(vz2[q], pzz, cpp);
                tq = fma2(vy2[q], pyy, tq);
                tq = fma2(vx2[q], pxx, tq);
                float2 a = unpack2(tq);
                rmin[2 * q]     = fminf(rmin[2 * q],     a.x);
                rmin[2 * q + 1] = fminf(rmin[2 * q + 1], a.y);
                u64 dq = add2(tq, cv2[q]);          // full d for the p-side
                float2 e = unpack2(dq);
                cmin[j] = fminf(cmin[j], fminf(e.x, e.y));
            }
        }

        // ---- dist2 partials: col tx+16j, across ty ----
#pragma unroll
        for (int j = 0; j < 8; j++)
            sred[(tx + 16 * j) * 17 + ty] = cmin[j];
        __syncthreads();

        if (tid < 128) {
            float mn = sred[tid * 17];
#pragma unroll
            for (int k = 1; k < 16; k++) mn = fminf(mn, sred[tid * 17 + k]);
            atomicMin(&g_d2[pb + t * 128 + tid], encf(mn));
        } else if (t + 1 < NTILE) {
            sp[(t + 1) & 1][tid - 128] = pn;        // overlap fill with reduce
        }
        __syncthreads();
    }

    // ---- dist1: once per block. rows 8ty+k, partials across tx ----
#pragma unroll
    for (int k = 0; k < 8; k++)
        sred[(8 * ty + k) * 17 + tx] = rmin[k];
    __syncthreads();
    if (tid < 128) {
        float mn = sred[tid * 17];
#pragma unroll
        for (int k = 1; k < 16; k++) mn = fminf(mn, sred[tid * 17 + k]);
        mn += g_vw[b * NV + n0 + tid].w;   // add ||v||^2 once, after the min
        atomicMin(&g_d1[b * NV + n0 + tid], encf(mn));
    }
}

// ------------------------ 3) final scalar reduction -------------------------
__global__ void final_kernel(float* __restrict__ out) {
    const int T = 256;
    __shared__ float sh[T];
    __shared__ float acc;
    int tid = threadIdx.x;
    if (tid == 0) acc = 0.f;

    for (int b = 0; b < BATCH; b++) {
        float s1 = 0.f;
        for (int n = tid; n < NV; n += T) s1 += decf(g_d1[b * NV + n]);
        sh[tid] = s1; __syncthreads();
        for (int s = T / 2; s > 0; s >>= 1) { if (tid < s) sh[tid] += sh[tid + s]; __syncthreads(); }
        float mean1 = sh[0] / (float)NV;
        __syncthreads();

        float s2 = 0.f, c2 = 0.f;
        for (int m = tid; m < NM; m += T) {
            float w = g_pw[b * NM + m].w;
            if (w < 1e9f) { s2 += decf(g_d2[b * NM + m]); c2 += 1.f; }
        }
        sh[tid] = s2; __syncthreads();
        for (int s = T / 2; s > 0; s >>= 1) { if (tid < s) sh[tid] += sh[tid + s]; __syncthreads(); }
        float sum2 = sh[0];
        __syncthreads();
        sh[tid] = c2; __syncthreads();
        for (int s = T / 2; s > 0; s >>= 1) { if (tid < s) sh[tid] += sh[tid + s]; __syncthreads(); }
        float cnt = sh[0];
        __syncthreads();

        if (tid == 0) acc += mean1 + sum2 / fmaxf(cnt, 1.f);
        __syncthreads();
    }
    if (tid == 0) out[0] = acc / (float)BATCH;
}

// ------------------------ launch --------------------------------------------
extern "C" void kernel_launch(void* const* d_in, const int* in_sizes, int n_in,
                              void* d_out, int out_size) {
    const float* vert = (const float*)d_in[0];
    const float* pc   = (const float*)d_in[1];
    if (in_sizes[0] == BATCH * 3 * NM) {   // defensive input identification
        vert = (const float*)d_in[1];
        pc   = (const float*)d_in[0];
    }

    pre_kernel<<<(BATCH * NM + 255) / 256, 256>>>(vert, pc);
    dim3 grid(NSTRIP, NV / 128, BATCH);
    chamfer_kernel<<<grid, 256>>>();
    final_kernel<<<1, 256>>>((float*)d_out);
}

// round 5
// speedup vs baseline: 1.3604x; 1.2407x over previous
#include <cuda_runtime.h>

#define BATCH 4
#define NV 4096
#define NM 8192
#define BIGF 1e10f
#define ENC_INF 0xFF7FFFFFu   // encoded FLT_MAX

#define NSTRIP 8               // m-strips per batch
#define STRIPM (NM / NSTRIP)   // 1024
#define BM     256             // p-cols per tile
#define NTILE  (STRIPM / BM)   // 4

typedef unsigned long long u64;

// ------------------------ scratch (device globals, no allocs) ---------------
__device__ float4   g_vw[BATCH * NV];   // (vx,vy,vz, ||v||^2)
__device__ float4   g_pw[BATCH * NM];   // (-2px,-2py,-2pz, ||p||^2) or (0,0,0,BIG)
__device__ unsigned g_d1[BATCH * NV];   // encoded min over p of d
__device__ unsigned g_d2[BATCH * NM];   // encoded min over v of d

// order-preserving float<->uint encoding so unsigned atomicMin == float min
__device__ __forceinline__ unsigned encf(float f) {
    unsigned u = __float_as_uint(f);
    return (u & 0x80000000u) ? ~u : (u | 0x80000000u);
}
__device__ __forceinline__ float decf(unsigned u) {
    return (u & 0x80000000u) ? __uint_as_float(u & 0x7FFFFFFFu)
                             : __uint_as_float(~u);
}

// ------------------------ packed f32x2 helpers ------------------------------
__device__ __forceinline__ u64 pack2(float lo, float hi) {
    u64 d;
    asm("mov.b64 %0, {%1, %2};" : "=l"(d) : "f"(lo), "f"(hi));
    return d;
}
__device__ __forceinline__ u64 fma2(u64 a, u64 b, u64 c) {
    u64 d;
    asm("fma.rn.f32x2 %0, %1, %2, %3;" : "=l"(d) : "l"(a), "l"(b), "l"(c));
    return d;
}
__device__ __forceinline__ u64 add2(u64 a, u64 b) {
    u64 d;
    asm("add.rn.f32x2 %0, %1, %2;" : "=l"(d) : "l"(a), "l"(b));
    return d;
}
// reinterpret (no asm -> ptxas can coalesce away)
__device__ __forceinline__ float2 asf2(u64 v) {
    union { u64 u; float2 f; } c; c.u = v; return c.f;
}

// ------------------------ 1) precompute + reset -----------------------------
__global__ void pre_kernel(const float* __restrict__ vert,
                           const float* __restrict__ pc,
                           float* __restrict__ out) {
    int t = blockIdx.x * blockDim.x + threadIdx.x;
    if (t == 0) out[0] = 0.f;
    if (t >= BATCH * NM) return;
    int b = t >> 13;          // / 8192
    int m = t & (NM - 1);

    float p0 = pc[(b * 3 + 0) * NM + m];
    float p1 = pc[(b * 3 + 1) * NM + m];
    float p2 = pc[(b * 3 + 2) * NM + m];
    bool valid = (p0 != 0.f) || (p1 != 0.f) || (p2 != 0.f);
    float cp = fmaf(p0, p0, fmaf(p1, p1, p2 * p2));
    float4 pw = valid ? make_float4(-2.f * p0, -2.f * p1, -2.f * p2, cp)
                      : make_float4(0.f, 0.f, 0.f, BIGF);
    g_pw[t] = pw;
    g_d2[t] = ENC_INF;

    if (m < NV) {
        int n = m;
        int i = n >> 6, k = n & 63;
        // vertices[b, c, i, 31, k]; shape (4,3,64,32,64)
        int base = ((b * 3) * 64 + i) * 2048 + 31 * 64 + k;
        float v0 = (vert[base]          - 0.5f) * 2.f;
        float v1 = (vert[base + 131072] - 0.5f) * 2.f;
        float v2 = (vert[base + 262144] - 0.5f) * 2.f;
        float cv = fmaf(v0, v0, fmaf(v1, v1, v2 * v2));
        g_vw[b * NV + n] = make_float4(v0, v1, v2, cv);
        g_d1[b * NV + n] = ENC_INF;
    }
}

// ------------------------ 2) fused pairwise min kernel ----------------------
// Block: 128 v-rows x 1024 p-cols (4 tiles of 256), 256 threads, grid=1024.
// Thread (ty,tx): ty=tid/16 owns v rows [8ty,8ty+8) as 4 packed pairs (regs);
//                 tx=tid%16 owns p cols tx+16j, j=0..15 of the current tile.
// d computed packed (3 fma2 + 1 add2); both mins taken on d (one unpack).
__global__ __launch_bounds__(256, 2) void chamfer_kernel() {
    __shared__ u64   spx[2][BM];
    __shared__ u64   spy[2][BM];
    __shared__ u64   spz[2][BM];
    __shared__ u64   spw[2][BM];
    __shared__ float sred[BM * 17];   // padded: conflict-free both phases

    int b    = blockIdx.z;
    int n0   = blockIdx.y * 128;
    int s    = blockIdx.x;                 // m-strip
    int pb   = b * NM + s * STRIPM;        // strip base in g_pw / g_d2
    int tid  = threadIdx.x;
    int ty   = tid >> 4;
    int tx   = tid & 15;

    // ---- my 8 v-rows as packed pairs (registers) ----
    u64 vx2[4], vy2[4], vz2[4], cv2[4];
#pragma unroll
    for (int q = 0; q < 4; q++) {
        int r = n0 + 8 * ty + 2 * q;
        float4 a = g_vw[b * NV + r];
        float4 c = g_vw[b * NV + r + 1];
        vx2[q] = pack2(a.x, c.x);
        vy2[q] = pack2(a.y, c.y);
        vz2[q] = pack2(a.z, c.z);
        cv2[q] = pack2(a.w, c.w);
    }

    float rmin[8];
#pragma unroll
    for (int k = 0; k < 8; k++) rmin[k] = 3.4e38f;

    // ---- prologue: fill tile 0 (all 256 threads, 1 entry each) ----
    {
        float4 p = g_pw[pb + tid];
        spx[0][tid] = pack2(p.x, p.x);
        spy[0][tid] = pack2(p.y, p.y);
        spz[0][tid] = pack2(p.z, p.z);
        spw[0][tid] = pack2(p.w, p.w);
    }
    __syncthreads();

    for (int t = 0; t < NTILE; t++) {
        int cur = t & 1, nxt = cur ^ 1;

        // prefetch next tile (threads 128..255, 2 entries each)
        float4 pn0, pn1;
        int u = tid - 128;
        if (tid >= 128 && t + 1 < NTILE) {
            pn0 = g_pw[pb + (t + 1) * BM + u];
            pn1 = g_pw[pb + (t + 1) * BM + u + 128];
        }

        float cmin[16];
#pragma unroll
        for (int j = 0; j < 16; j++) cmin[j] = 3.4e38f;

#pragma unroll
        for (int j = 0; j < 16; j++) {
            int c = tx + 16 * j;
            u64 pxx = spx[cur][c];
            u64 pyy = spy[cur][c];
            u64 pzz = spz[cur][c];
            u64 cpp = spw[cur][c];
#pragma unroll
            for (int q = 0; q < 4; q++) {
                // d = cv + cp - 2 v.p   (both rows of the pair)
                u64 tq = fma2(vz2[q], pzz, cpp);
                tq = fma2(vy2[q], pyy, tq);
                tq = fma2(vx2[q], pxx, tq);
                u64 dq = add2(tq, cv2[q]);
                float2 e = asf2(dq);
                rmin[2 * q]     = fminf(rmin[2 * q],     e.x);
                rmin[2 * q + 1] = fminf(rmin[2 * q + 1], e.y);
                cmin[j] = fminf(cmin[j], fminf(e.x, e.y));
            }
        }

        // commit prefetched tile (safe: everyone is past tile t-1's reads)
        if (tid >= 128 && t + 1 < NTILE) {
            spx[nxt][u] = pack2(pn0.x, pn0.x);  spx[nxt][u + 128] = pack2(pn1.x, pn1.x);
            spy[nxt][u] = pack2(pn0.y, pn0.y);  spy[nxt][u + 128] = pack2(pn1.y, pn1.y);
            spz[nxt][u] = pack2(pn0.z, pn0.z);  spz[nxt][u + 128] = pack2(pn1.z, pn1.z);
            spw[nxt][u] = pack2(pn0.w, pn0.w);  spw[nxt][u + 128] = pack2(pn1.w, pn1.w);
        }

        // ---- dist2 partials: col tx+16j, across ty ----
#pragma unroll
        for (int j = 0; j < 16; j++)
            sred[(tx + 16 * j) * 17 + ty] = cmin[j];
        __syncthreads();

        {   // every thread reduces one column
            float mn = sred[tid * 17];
#pragma unroll
            for (int k = 1; k < 16; k++) mn = fminf(mn, sred[tid * 17 + k]);
            atomicMin(&g_d2[pb + t * BM + tid], encf(mn));
        }
        __syncthreads();
    }

    // ---- dist1: once per block. rows 8ty+k, partials across tx ----
#pragma unroll
    for (int k = 0; k < 8; k++)
        sred[(8 * ty + k) * 17 + tx] = rmin[k];
    __syncthreads();
    if (tid < 128) {
        float mn = sred[tid * 17];
#pragma unroll
        for (int k = 1; k < 16; k++) mn = fminf(mn, sred[tid * 17 + k]);
        atomicMin(&g_d1[b * NV + n0 + tid], encf(mn));
    }
}

// ------------------------ 3) final scalar reduction -------------------------
// one block per batch; atomicAdd into out (zeroed by pre_kernel)
__global__ void final_kernel(float* __restrict__ out) {
    const int T = 256;
    __shared__ float sh[T];
    int tid = threadIdx.x;
    int b = blockIdx.x;

    float s1 = 0.f;
    for (int n = tid; n < NV; n += T) s1 += decf(g_d1[b * NV + n]);
    sh[tid] = s1; __syncthreads();
    for (int s = T / 2; s > 0; s >>= 1) { if (tid < s) sh[tid] += sh[tid + s]; __syncthreads(); }
    float mean1 = sh[0] / (float)NV;
    __syncthreads();

    float s2 = 0.f, c2 = 0.f;
    for (int m = tid; m < NM; m += T) {
        float w = g_pw[b * NM + m].w;
        if (w < 1e9f) { s2 += decf(g_d2[b * NM + m]); c2 += 1.f; }
    }
    sh[tid] = s2; __syncthreads();
    for (int s = T / 2; s > 0; s >>= 1) { if (tid < s) sh[tid] += sh[tid + s]; __syncthreads(); }
    float sum2 = sh[0];
    __syncthreads();
    sh[tid] = c2; __syncthreads();
    for (int s = T / 2; s > 0; s >>= 1) { if (tid < s) sh[tid] += sh[tid + s]; __syncthreads(); }
    float cnt = sh[0];

    if (tid == 0)
        atomicAdd(out, (mean1 + sum2 / fmaxf(cnt, 1.f)) / (float)BATCH);
}

// ------------------------ launch --------------------------------------------
extern "C" void kernel_launch(void* const* d_in, const int* in_sizes, int n_in,
                              void* d_out, int out_size) {
    const float* vert = (const float*)d_in[0];
    const float* pc   = (const float*)d_in[1];
    if (in_sizes[0] == BATCH * 3 * NM) {   // defensive input identification
        vert = (const float*)d_in[1];
        pc   = (const float*)d_in[0];
    }

    pre_kernel<<<(BATCH * NM + 255) / 256, 256>>>(vert, pc, (float*)d_out);
    dim3 grid(NSTRIP, NV / 128, BATCH);
    chamfer_kernel<<<grid, 256>>>();
    final_kernel<<<BATCH, 256>>>((float*)d_out);
}

// round 6
// speedup vs baseline: 1.4226x; 1.0458x over previous
#include <cuda_runtime.h>

#define BATCH 4
#define NV 4096
#define NM 8192
#define BIGF 1e10f

#define NSTRIP 8               // m-strips per batch
#define STRIPM (NM / NSTRIP)   // 1024
#define BM     128             // p-cols per tile
#define NTILE  (STRIPM / BM)   // 8
#define NVB    (NV / 128)      // 32 v-row blocks

typedef unsigned long long u64;

// ------------------------ scratch (device globals, no allocs) ---------------
// partial mins, plain stores (each element written by exactly one block)
__device__ float g_d1p[NSTRIP][BATCH * NV];   // min over a strip's p, per v row
__device__ float g_d2p[NVB][BATCH * NM];      // min over a 128-row v block, per p col
__device__ float g_sum1[BATCH], g_sum2[BATCH], g_cnt[BATCH];
__device__ unsigned g_done;

// ------------------------ packed f32x2 helpers ------------------------------
__device__ __forceinline__ u64 pack2(float lo, float hi) {
    u64 d;
    asm("mov.b64 %0, {%1, %2};" : "=l"(d) : "f"(lo), "f"(hi));
    return d;
}
__device__ __forceinline__ u64 fma2(u64 a, u64 b, u64 c) {
    u64 d;
    asm("fma.rn.f32x2 %0, %1, %2, %3;" : "=l"(d) : "l"(a), "l"(b), "l"(c));
    return d;
}
__device__ __forceinline__ u64 add2(u64 a, u64 b) {
    u64 d;
    asm("add.rn.f32x2 %0, %1, %2;" : "=l"(d) : "l"(a), "l"(b));
    return d;
}
__device__ __forceinline__ float2 asf2(u64 v) {
    union { u64 u; float2 f; } c; c.u = v; return c.f;
}

// ------------------------ 1) fused transform + pairwise min ------------------
// Block: 128 v-rows x 1024 p-cols (8 tiles of 128), 256 threads, grid=1024.
// Transforms v (top-surface gather) and p (dup-packed) in-kernel: no pre pass.
// Partial mins written with plain stores: no atomics, no init pass.
__global__ __launch_bounds__(256, 3) void chamfer_kernel(
        const float* __restrict__ vert, const float* __restrict__ pc) {
    __shared__ u64   spx[2][BM];
    __shared__ u64   spy[2][BM];
    __shared__ u64   spz[2][BM];
    __shared__ u64   spw[2][BM];
    __shared__ float sred[128 * 17];   // padded reduction scratch
    __shared__ __align__(16) float svx[128], svy[128], svz[128], scv[128];

    int b   = blockIdx.z;
    int y   = blockIdx.y;
    int n0  = y * 128;
    int s   = blockIdx.x;
    int mb0 = s * STRIPM;
    int tid = threadIdx.x;
    int ty  = tid >> 4;
    int tx  = tid & 15;

    // one block zeroes the final-stage accumulators (nobody reads them in K1)
    if (blockIdx.x == 0 && blockIdx.y == 0 && blockIdx.z == 0 && tid < BATCH) {
        g_sum1[tid] = 0.f; g_sum2[tid] = 0.f; g_cnt[tid] = 0.f;
        if (tid == 0) g_done = 0u;
    }

    // ---- transform my v rows (top surface gather) + p tile 0 ----
    if (tid < 128) {
        int r = n0 + tid;
        int i = r >> 6, k = r & 63;
        // vertices[b, c, i, 31, k]; shape (4,3,64,32,64)
        int base = ((b * 3) * 64 + i) * 2048 + 31 * 64 + k;
        float v0 = (vert[base]          - 0.5f) * 2.f;
        float v1 = (vert[base + 131072] - 0.5f) * 2.f;
        float v2 = (vert[base + 262144] - 0.5f) * 2.f;
        svx[tid] = v0; svy[tid] = v1; svz[tid] = v2;
        scv[tid] = fmaf(v0, v0, fmaf(v1, v1, v2 * v2));
    } else {
        int u = tid - 128;
        int m = mb0 + u;
        float p0 = pc[(b * 3 + 0) * NM + m];
        float p1 = pc[(b * 3 + 1) * NM + m];
        float p2 = pc[(b * 3 + 2) * NM + m];
        bool valid = (p0 != 0.f) || (p1 != 0.f) || (p2 != 0.f);
        float cp = valid ? fmaf(p0, p0, fmaf(p1, p1, p2 * p2)) : BIGF;
        spx[0][u] = pack2(-2.f * p0, -2.f * p0);
        spy[0][u] = pack2(-2.f * p1, -2.f * p1);
        spz[0][u] = pack2(-2.f * p2, -2.f * p2);
        spw[0][u] = pack2(cp, cp);
    }
    __syncthreads();

    // ---- my 8 v-rows as packed pairs (LDS.64 from SoA smem) ----
    u64 vx2[4], vy2[4], vz2[4], cv2[4];
#pragma unroll
    for (int q = 0; q < 4; q++) {
        int r = 8 * ty + 2 * q;
        vx2[q] = *(const u64*)&svx[r];
        vy2[q] = *(const u64*)&svy[r];
        vz2[q] = *(const u64*)&svz[r];
        cv2[q] = *(const u64*)&scv[r];
    }

    float rmin[8];
#pragma unroll
    for (int k = 0; k < 8; k++) rmin[k] = 3.4e38f;

    for (int t = 0; t < NTILE; t++) {
        int cur = t & 1, nxt = cur ^ 1;

        // prefetch + transform next tile (threads 128..255)
        float pnx, pny, pnz, pnw;
        int u = tid - 128;
        if (tid >= 128 && t + 1 < NTILE) {
            int m = mb0 + (t + 1) * BM + u;
            float p0 = pc[(b * 3 + 0) * NM + m];
            float p1 = pc[(b * 3 + 1) * NM + m];
            float p2 = pc[(b * 3 + 2) * NM + m];
            bool valid = (p0 != 0.f) || (p1 != 0.f) || (p2 != 0.f);
            pnw = valid ? fmaf(p0, p0, fmaf(p1, p1, p2 * p2)) : BIGF;
            pnx = -2.f * p0; pny = -2.f * p1; pnz = -2.f * p2;
        }

        float cmin[8];
#pragma unroll
        for (int j = 0; j < 8; j++) cmin[j] = 3.4e38f;

#pragma unroll
        for (int j = 0; j < 8; j++) {
            int c = tx + 16 * j;
            u64 pxx = spx[cur][c];
            u64 pyy = spy[cur][c];
            u64 pzz = spz[cur][c];
            u64 cpp = spw[cur][c];
#pragma unroll
            for (int q = 0; q < 4; q++) {
                // tq = cp - 2 v.p  (both rows of the pair)
                u64 tq = fma2(vz2[q], pzz, cpp);
                tq = fma2(vy2[q], pyy, tq);
                tq = fma2(vx2[q], pxx, tq);
                float2 a = asf2(tq);
                rmin[2 * q]     = fminf(rmin[2 * q],     a.x);   // cv added at end
                rmin[2 * q + 1] = fminf(rmin[2 * q + 1], a.y);
                float2 e = asf2(add2(tq, cv2[q]));               // full d for p-side
                cmin[j] = fminf(cmin[j], fminf(e.x, e.y));
            }
        }

        // commit prefetched tile (everyone is past tile t-1's reads)
        if (tid >= 128 && t + 1 < NTILE) {
            spx[nxt][u] = pack2(pnx, pnx);
            spy[nxt][u] = pack2(pny, pny);
            spz[nxt][u] = pack2(pnz, pnz);
            spw[nxt][u] = pack2(pnw, pnw);
        }

        // ---- dist2 partials: col tx+16j, across ty ----
#pragma unroll
        for (int j = 0; j < 8; j++)
            sred[(tx + 16 * j) * 17 + ty] = cmin[j];
        __syncthreads();

        if (tid < 128) {
            float mn = sred[tid * 17];
#pragma unroll
            for (int k = 1; k < 16; k++) mn = fminf(mn, sred[tid * 17 + k]);
            g_d2p[y][b * NM + mb0 + t * BM + tid] = mn;   // plain store
        }
        __syncthreads();
    }

    // ---- dist1 partial: once per block ----
#pragma unroll
    for (int k = 0; k < 8; k++)
        sred[(8 * ty + k) * 17 + tx] = rmin[k];
    __syncthreads();
    if (tid < 128) {
        float mn = sred[tid * 17];
#pragma unroll
        for (int k = 1; k < 16; k++) mn = fminf(mn, sred[tid * 17 + k]);
        g_d1p[s][b * NV + n0 + tid] = mn + scv[tid];      // plain store
    }
}

// ------------------------ 2) final reduction --------------------------------
// 64 blocks: 16 per batch; completion counter -> last block writes out.
__global__ void final_kernel(const float* __restrict__ pc,
                             float* __restrict__ out) {
    __shared__ float sh[256];
    __shared__ bool last;
    int tid  = threadIdx.x;
    int b    = blockIdx.x >> 4;
    int part = blockIdx.x & 15;

    // dist1: 256 v rows per block, 1 per thread
    float s1;
    {
        int n = part * 256 + tid;
        float mn = g_d1p[0][b * NV + n];
#pragma unroll
        for (int s = 1; s < NSTRIP; s++) mn = fminf(mn, g_d1p[s][b * NV + n]);
        s1 = mn;
    }

    // dist2: 512 p cols per block, 2 per thread
    float s2 = 0.f, c2 = 0.f;
#pragma unroll
    for (int mm = 0; mm < 2; mm++) {
        int m = part * 512 + mm * 256 + tid;
        float mn = g_d2p[0][b * NM + m];
#pragma unroll
        for (int yy = 1; yy < NVB; yy++) mn = fminf(mn, g_d2p[yy][b * NM + m]);
        float p0 = pc[(b * 3 + 0) * NM + m];
        float p1 = pc[(b * 3 + 1) * NM + m];
        float p2 = pc[(b * 3 + 2) * NM + m];
        if ((p0 != 0.f) || (p1 != 0.f) || (p2 != 0.f)) { s2 += mn; c2 += 1.f; }
    }

    // block reduction of s1, s2, c2
    sh[tid] = s1; __syncthreads();
    for (int s = 128; s > 0; s >>= 1) { if (tid < s) sh[tid] += sh[tid + s]; __syncthreads(); }
    float t1 = sh[0]; __syncthreads();
    sh[tid] = s2; __syncthreads();
    for (int s = 128; s > 0; s >>= 1) { if (tid < s) sh[tid] += sh[tid + s]; __syncthreads(); }
    float t2 = sh[0]; __syncthreads();
    sh[tid] = c2; __syncthreads();
    for (int s = 128; s > 0; s >>= 1) { if (tid < s) sh[tid] += sh[tid + s]; __syncthreads(); }
    float tc = sh[0];

    if (tid == 0) {
        atomicAdd(&g_sum1[b], t1);
        atomicAdd(&g_sum2[b], t2);
        atomicAdd(&g_cnt[b],  tc);
        __threadfence();
        unsigned done = atomicAdd(&g_done, 1u);
        last = (done == gridDim.x - 1);
    }
    __syncthreads();

    if (last && tid == 0) {
        float acc = 0.f;
        for (int bb = 0; bb < BATCH; bb++)
            acc += g_sum1[bb] / (float)NV + g_sum2[bb] / fmaxf(g_cnt[bb], 1.f);
        out[0] = acc / (float)BATCH;
    }
}

// ------------------------ launch --------------------------------------------
extern "C" void kernel_launch(void* const* d_in, const int* in_sizes, int n_in,
                              void* d_out, int out_size) {
    const float* vert = (const float*)d_in[0];
    const float* pc   = (const float*)d_in[1];
    if (in_sizes[0] == BATCH * 3 * NM) {   // defensive input identification
        vert = (const float*)d_in[1];
        pc   = (const float*)d_in[0];
    }

    dim3 grid(NSTRIP, NVB, BATCH);
    chamfer_kernel<<<grid, 256>>>(vert, pc);
    final_kernel<<<64, 256>>>(pc, (float*)d_out);
}